// round 8
// baseline (speedup 1.0000x reference)
#include <cuda_runtime.h>
#include <cuda_bf16.h>
#include <cstdint>

// Embedding gather: out[t, :] = weight[token_ids[t], :]   (rows 4 KB fp32)
// d_in[0] = token_ids (int32) [8192], d_in[1] = weight [32000,1024] fp32
//
// Parallel bulk-DMA: 2048 CTAs x 4 tokens. Each CTA issues ALL 4 row loads
// (cp.async.bulk g2s, mbarrier complete_tx) immediately, then stores each
// row back (cp.async.bulk s2g) as it lands. No stage reuse; register-free
// data movement on the TMA path (bypasses L1tex wavefront queue).

static constexpr int ROW_BYTES = 4096;
static constexpr int TPC       = 4;       // tokens per CTA == stages

__device__ __forceinline__ uint32_t smem_u32(const void* p) {
    return (uint32_t)__cvta_generic_to_shared(p);
}

__device__ __forceinline__ void mbar_init(uint32_t mbar, uint32_t count) {
    asm volatile("mbarrier.init.shared::cta.b64 [%0], %1;" :: "r"(mbar), "r"(count) : "memory");
}

__device__ __forceinline__ void mbar_expect_tx(uint32_t mbar, uint32_t bytes) {
    asm volatile("mbarrier.arrive.expect_tx.shared::cta.b64 _, [%0], %1;"
                 :: "r"(mbar), "r"(bytes) : "memory");
}

__device__ __forceinline__ void mbar_wait_parity0(uint32_t mbar) {
    asm volatile(
        "{\n\t"
        ".reg .pred P;\n\t"
        "WAIT_%=:\n\t"
        "mbarrier.try_wait.parity.acquire.cta.shared::cta.b64 P, [%0], 0, 0x989680;\n\t"
        "@P bra.uni DONE_%=;\n\t"
        "bra.uni WAIT_%=;\n\t"
        "DONE_%=:\n\t"
        "}"
        :: "r"(mbar) : "memory");
}

__device__ __forceinline__ void bulk_load_g2s(uint32_t smem_dst, const void* gmem_src,
                                              uint32_t bytes, uint32_t mbar) {
    asm volatile(
        "cp.async.bulk.shared::cta.global.mbarrier::complete_tx::bytes [%0], [%1], %2, [%3];"
        :: "r"(smem_dst), "l"(gmem_src), "r"(bytes), "r"(mbar) : "memory");
}

__device__ __forceinline__ void bulk_store_s2g(void* gmem_dst, uint32_t smem_src,
                                               uint32_t bytes) {
    asm volatile(
        "cp.async.bulk.global.shared::cta.bulk_group [%0], [%1], %2;"
        :: "l"(gmem_dst), "r"(smem_src), "r"(bytes) : "memory");
}

__global__ __launch_bounds__(32)
void embedding_dma_kernel(const int* __restrict__ token_ids,
                          const char* __restrict__ weight,
                          char* __restrict__ out) {
    __shared__ __align__(1024) unsigned char buf[TPC * ROW_BYTES];
    __shared__ __align__(8)    uint64_t      mbar[TPC];
    __shared__                 int           sids[TPC];

    const int lane = threadIdx.x;
    const int t0   = blockIdx.x * TPC;

    // Cooperative independent index loads.
    if (lane < TPC) sids[lane] = __ldg(token_ids + t0 + lane);
    if (lane == 0) {
#pragma unroll
        for (int s = 0; s < TPC; ++s) mbar_init(smem_u32(&mbar[s]), 1);
    }
    __syncwarp();

    if (lane != 0) return;   // single DMA driver thread; engines move the data

    const uint32_t buf_base  = smem_u32(buf);
    const uint32_t mbar_base = smem_u32(mbar);

    // Issue ALL loads up front (full MLP, no dependencies).
#pragma unroll
    for (int s = 0; s < TPC; ++s) {
        mbar_expect_tx(mbar_base + 8u * s, ROW_BYTES);
        bulk_load_g2s(buf_base + (uint32_t)s * ROW_BYTES,
                      weight + (size_t)sids[s] * ROW_BYTES,
                      ROW_BYTES, mbar_base + 8u * s);
    }

    // Store each row as it completes (in order; loads overlap regardless).
#pragma unroll
    for (int s = 0; s < TPC; ++s) {
        mbar_wait_parity0(mbar_base + 8u * s);
        bulk_store_s2g(out + (size_t)(t0 + s) * ROW_BYTES,
                       buf_base + (uint32_t)s * ROW_BYTES, ROW_BYTES);
    }
    asm volatile("cp.async.bulk.commit_group;" ::: "memory");
    asm volatile("cp.async.bulk.wait_group 0;" ::: "memory");
}

extern "C" void kernel_launch(void* const* d_in, const int* in_sizes, int n_in,
                              void* d_out, int out_size) {
    const int* token_ids = (const int*)d_in[0];
    const char* weight   = (const char*)d_in[1];
    char* out            = (char*)d_out;

    int n_tokens = in_sizes[0];          // 8192
    int n_ctas   = n_tokens / TPC;       // 2048

    embedding_dma_kernel<<<n_ctas, 32>>>(token_ids, weight, out);
}

// round 9
// speedup vs baseline: 1.2799x; 1.2799x over previous
#include <cuda_runtime.h>
#include <cuda_bf16.h>
#include <cstdint>

// Embedding gather: out[t, :] = weight[token_ids[t], :]
// d_in[0] = token_ids (int32) [8192], d_in[1] = weight fp32 [32000,1024]
// d_out = fp32 [8192,1024]
//
// Forced-MLP variant: 4 tokens per CTA, 256 threads. The 4 gather loads are
// issued as consecutive *volatile* inline-asm v4 loads, which ptxas may not
// reorder — guaranteeing 4 independent LDG.128s in flight per thread before
// any store. grid = 2048 CTAs (~2 waves).

static constexpr int D4      = 256;   // float4s per row
static constexpr int THREADS = 256;
static constexpr int TPC     = 4;

__global__ __launch_bounds__(THREADS)
void embedding_gather_mlp4_kernel(const int* __restrict__ token_ids,
                                  const float4* __restrict__ weight,
                                  float4* __restrict__ out) {
    const int t_base = blockIdx.x * TPC;
    const int tid = threadIdx.x;

    // Independent index loads (all 4 issued up front).
    int r0 = __ldg(token_ids + t_base + 0);
    int r1 = __ldg(token_ids + t_base + 1);
    int r2 = __ldg(token_ids + t_base + 2);
    int r3 = __ldg(token_ids + t_base + 3);

    const float4* s0 = weight + (size_t)r0 * D4 + tid;
    const float4* s1 = weight + (size_t)r1 * D4 + tid;
    const float4* s2 = weight + (size_t)r2 * D4 + tid;
    const float4* s3 = weight + (size_t)r3 * D4 + tid;

    float a0, b0, c0, d0, a1, b1, c1, d1;
    float a2, b2, c2, d2, a3, b3, c3, d3;

    // Volatile asm: ptxas preserves issue order -> 4 LDGs in flight.
    asm volatile("ld.global.nc.v4.f32 {%0,%1,%2,%3}, [%4];"
                 : "=f"(a0), "=f"(b0), "=f"(c0), "=f"(d0) : "l"(s0));
    asm volatile("ld.global.nc.v4.f32 {%0,%1,%2,%3}, [%4];"
                 : "=f"(a1), "=f"(b1), "=f"(c1), "=f"(d1) : "l"(s1));
    asm volatile("ld.global.nc.v4.f32 {%0,%1,%2,%3}, [%4];"
                 : "=f"(a2), "=f"(b2), "=f"(c2), "=f"(d2) : "l"(s2));
    asm volatile("ld.global.nc.v4.f32 {%0,%1,%2,%3}, [%4];"
                 : "=f"(a3), "=f"(b3), "=f"(c3), "=f"(d3) : "l"(s3));

    float4* dst = out + (size_t)t_base * D4 + tid;
    asm volatile("st.global.v4.f32 [%0], {%1,%2,%3,%4};"
                 :: "l"(dst + 0 * D4), "f"(a0), "f"(b0), "f"(c0), "f"(d0) : "memory");
    asm volatile("st.global.v4.f32 [%0], {%1,%2,%3,%4};"
                 :: "l"(dst + 1 * D4), "f"(a1), "f"(b1), "f"(c1), "f"(d1) : "memory");
    asm volatile("st.global.v4.f32 [%0], {%1,%2,%3,%4};"
                 :: "l"(dst + 2 * D4), "f"(a2), "f"(b2), "f"(c2), "f"(d2) : "memory");
    asm volatile("st.global.v4.f32 [%0], {%1,%2,%3,%4};"
                 :: "l"(dst + 3 * D4), "f"(a3), "f"(b3), "f"(c3), "f"(d3) : "memory");
}

extern "C" void kernel_launch(void* const* d_in, const int* in_sizes, int n_in,
                              void* d_out, int out_size) {
    const int* token_ids = (const int*)d_in[0];
    const float4* weight = (const float4*)d_in[1];
    float4* out          = (float4*)d_out;

    int n_tokens = in_sizes[0];        // 8192
    int n_ctas   = n_tokens / TPC;     // 2048

    embedding_gather_mlp4_kernel<<<n_ctas, THREADS>>>(token_ids, weight, out);
}